// round 12
// baseline (speedup 1.0000x reference)
#include <cuda_runtime.h>
#include <cuda_fp16.h>
#include <math.h>
#include <cstdint>

#define NTOK 4096      // T*B
#define DDIM 1024
#define HDIM 2048
#define ODIM 1024
#define NEXP 8
#define EMAX 4096      // max tokens per expert

// fp16 panels: A [E][EMAX][Kd] (row-major K), B [E][Nd][Kd] (N rows, K contig).

// ---------------- scratch (device globals; no allocation allowed) ----------
__device__ float g_xn[(size_t)NTOK * DDIM];                          // 16 MB
__device__ float g_y[(size_t)2 * NTOK * ODIM];                       // 32 MB
__device__ int   g_cnt[NEXP];
__device__ int   g_slots[NEXP * NTOK];
__device__ float g_prob[2 * NTOK];
__device__ __half g_A1[(size_t)NEXP * EMAX * DDIM];                  // 67 MB
__device__ __half g_A2[(size_t)NEXP * EMAX * HDIM];                  // 134 MB
__device__ __half g_B1[(size_t)NEXP * HDIM * DDIM];                  // 33.5 MB
__device__ __half g_B2[(size_t)NEXP * ODIM * HDIM];                  // 33.5 MB

// ---------------- PTX helpers ----------------------------------------------
__device__ __forceinline__ uint32_t smem_to_u32(const void* p) {
    uint32_t a;
    asm("{ .reg .u64 t; cvta.to.shared.u64 t, %1; cvt.u32.u64 %0, t; }" : "=r"(a) : "l"(p));
    return a;
}
#define CP_ASYNC16(saddr, gptr) \
    asm volatile("cp.async.cg.shared.global [%0], [%1], 16;" :: "r"(saddr), "l"(gptr))
#define CP_COMMIT() asm volatile("cp.async.commit_group;" ::: "memory")
#define CP_WAIT1()  asm volatile("cp.async.wait_group 1;" ::: "memory")
#define LDSM_X4(R, addr) \
    asm volatile("ldmatrix.sync.aligned.m8n8.x4.shared.b16 {%0,%1,%2,%3}, [%4];" \
                 : "=r"((R)[0]), "=r"((R)[1]), "=r"((R)[2]), "=r"((R)[3]) : "r"(addr))
#define MMAH16816(D, A, B0, B1) \
    asm volatile("mma.sync.aligned.m16n8k16.row.col.f32.f16.f16.f32 " \
        "{%0,%1,%2,%3}, {%4,%5,%6,%7}, {%8,%9}, {%0,%1,%2,%3};" \
        : "+f"((D)[0]), "+f"((D)[1]), "+f"((D)[2]), "+f"((D)[3]) \
        : "r"((A)[0]), "r"((A)[1]), "r"((A)[2]), "r"((A)[3]), "r"(B0), "r"(B1))

__device__ __forceinline__ float gelu_exact(float v) {
    return 0.5f * v * (1.0f + erff(v * 0.70710678118654752440f));
}
__device__ __forceinline__ uint32_t pack_h2(float a, float b) {
    __half2 h = __floats2half2_rn(a, b);
    return *(uint32_t*)&h;
}

// ---------------- kernel 0: zero counters ----------------------------------
__global__ void zero_kernel() {
    if (threadIdx.x < NEXP) g_cnt[threadIdx.x] = 0;
}

// ---------------- kernel 1: LN + router + top2 + scatter -------------------
__global__ __launch_bounds__(256)
void ln_router_kernel(const float* __restrict__ x,
                      const float* __restrict__ gamma,
                      const float* __restrict__ beta,
                      const float* __restrict__ rw,
                      float* __restrict__ logits_out,
                      int write_logits)
{
    const int n = blockIdx.x;
    const int tid = threadIdx.x;
    __shared__ float sx[DDIM];
    __shared__ float red[256];
    __shared__ float sstat[2];
    __shared__ float lg[NEXP];

    const float* xr = x + (size_t)n * DDIM;
    float s = 0.f;
    for (int i = tid; i < DDIM; i += 256) { float v = xr[i]; sx[i] = v; s += v; }
    red[tid] = s; __syncthreads();
    for (int st = 128; st > 0; st >>= 1) { if (tid < st) red[tid] += red[tid + st]; __syncthreads(); }
    if (tid == 0) sstat[0] = red[0] * (1.0f / DDIM);
    __syncthreads();
    const float mu = sstat[0];
    float s2 = 0.f;
    for (int i = tid; i < DDIM; i += 256) { float v = sx[i] - mu; s2 += v * v; }
    red[tid] = s2; __syncthreads();
    for (int st = 128; st > 0; st >>= 1) { if (tid < st) red[tid] += red[tid + st]; __syncthreads(); }
    if (tid == 0) sstat[1] = rsqrtf(red[0] * (1.0f / DDIM) + 1e-5f);
    __syncthreads();
    const float rstd = sstat[1];
    for (int i = tid; i < DDIM; i += 256) {
        float v = (sx[i] - mu) * rstd * gamma[i] + beta[i];
        sx[i] = v;
        g_xn[(size_t)n * DDIM + i] = v;
    }
    __syncthreads();

    const int w = tid >> 5, lane = tid & 31;
    {
        const float* r = rw + w * DDIM;
        float p = 0.f;
        for (int i = lane; i < DDIM; i += 32) p += sx[i] * r[i];
        #pragma unroll
        for (int o = 16; o > 0; o >>= 1) p += __shfl_down_sync(0xffffffffu, p, o);
        if (lane == 0) lg[w] = p;
    }
    __syncthreads();

    if (tid == 0) {
        if (write_logits) {
            #pragma unroll
            for (int e = 0; e < NEXP; e++) logits_out[(size_t)n * NEXP + e] = lg[e];
        }
        int i0 = 0;
        #pragma unroll
        for (int e = 1; e < NEXP; e++) if (lg[e] > lg[i0]) i0 = e;
        int i1 = (i0 == 0) ? 1 : 0;
        #pragma unroll
        for (int e = 0; e < NEXP; e++) if (e != i0 && lg[e] > lg[i1]) i1 = e;
        float q = expf(lg[i1] - lg[i0]);
        float inv = 1.0f / (1.0f + q);
        g_prob[2 * n]     = inv;
        g_prob[2 * n + 1] = q * inv;
        int p0 = atomicAdd(&g_cnt[i0], 1); g_slots[i0 * NTOK + p0] = 2 * n;
        int p1 = atomicAdd(&g_cnt[i1], 1); g_slots[i1 * NTOK + p1] = 2 * n + 1;
    }
}

// ---------------- kernel 2: pack tokens into per-expert A1 (fp16) ----------
__global__ __launch_bounds__(256)
void pack1_kernel()
{
    const int e = blockIdx.y;
    const int m0 = blockIdx.x * 128;
    const int cnt = g_cnt[e];
    if (m0 >= cnt) return;
    const int tid = threadIdx.x;
    __half* outp = g_A1 + ((size_t)e * EMAX) * DDIM;
    for (int idx = tid; idx < 128 * 256; idx += 256) {
        int r = idx >> 8;
        int c4 = idx & 255;
        int row = m0 + r;
        if (row >= cnt) continue;
        int token = g_slots[e * NTOK + row] >> 1;
        float4 v = ((const float4*)g_xn)[(size_t)token * 256 + c4];
        uint2 hp = make_uint2(pack_h2(v.x, v.y), pack_h2(v.z, v.w));
        *(uint2*)&outp[(size_t)row * DDIM + c4 * 4] = hp;
    }
}

// ---------------- kernel 3: weight transpose to fp16 -----------------------
// W [E][Kd][Nd] (fp32) -> B [E][Nd][Kd] (fp16)
template<int LAYER>
__global__ __launch_bounds__(256)
void wcvt_kernel(const float* __restrict__ W)
{
    constexpr int Kd = (LAYER == 1) ? DDIM : HDIM;
    constexpr int Nd = (LAYER == 1) ? HDIM : ODIM;
    __half* Bout = (LAYER == 1) ? g_B1 : g_B2;
    const int e = blockIdx.z;
    const int d0 = blockIdx.x * 32;   // K base
    const int h0 = blockIdx.y * 32;   // N base
    __shared__ float st[32][33];
    const int tid = threadIdx.x;
    {
        int dl = tid >> 3, q = tid & 7;
        float4 v = *(const float4*)(W + ((size_t)e * Kd + d0 + dl) * Nd + h0 + q * 4);
        st[dl][q * 4 + 0] = v.x; st[dl][q * 4 + 1] = v.y;
        st[dl][q * 4 + 2] = v.z; st[dl][q * 4 + 3] = v.w;
    }
    __syncthreads();
    const int n = tid >> 3, j0 = (tid & 7) * 4;
    uint2 pk = make_uint2(pack_h2(st[j0][n], st[j0 + 1][n]),
                          pack_h2(st[j0 + 2][n], st[j0 + 3][n]));
    *(uint2*)&Bout[((size_t)e * Nd + h0 + n) * Kd + d0 + j0] = pk;
}

// ---------------- kernels 4/5: grouped fp16 GEMM via mma.sync --------------
// CTA tile 128x128, 4 warps in 2x2 grid, warp tile 64x64 (minimizes smem
// reads per MMA: each A/B panel read exactly 2x). K-chunk = 64; 3-stage
// cp.async. 128 threads, 2 CTAs/SM.
template<int LAYER>
__global__ __launch_bounds__(128, 2)
void mma_gemm(const float* __restrict__ bias_all)
{
    constexpr int Kd = (LAYER == 1) ? DDIM : HDIM;
    constexpr int Nd = (LAYER == 1) ? HDIM : ODIM;
    constexpr int NCH = Kd / 64;
    constexpr int STAGE_BYTES = 32768;   // A 16K + B 16K
    const __half* __restrict__ Aall = (LAYER == 1) ? g_A1 : g_A2;
    const __half* __restrict__ Ball = (LAYER == 1) ? g_B1 : g_B2;

    const int e = blockIdx.z;
    const int cnt = g_cnt[e];
    const int m0 = blockIdx.x * 128;
    if (m0 >= cnt) return;
    const int n0 = blockIdx.y * 128;

    extern __shared__ __align__(1024) char smem[];
    const uint32_t smem_u = smem_to_u32(smem);

    const int tid = threadIdx.x;
    const int lane = tid & 31;
    const int wid = tid >> 5;
    const int wm = wid >> 1;          // 0..1 -> 64-row block
    const int wn = wid & 1;           // 0..1 -> 64-col block

    const size_t rstride = Kd;   // elements
    const __half* Abase = Aall + ((size_t)e * EMAX + m0) * rstride;
    const __half* Bbase = Ball + ((size_t)e * Nd + n0) * rstride;

    const int lr = tid >> 3;          // 16 rows covered per sweep
    const int lch = tid & 7;          // 16B chunk in 128B row
    const uint32_t lsw = (uint32_t)(lch * 16) ^ (uint32_t)((lr & 7) << 4);

    float acc[4][8][4];
    #pragma unroll
    for (int i = 0; i < 4; i++)
        #pragma unroll
        for (int j = 0; j < 8; j++)
            #pragma unroll
            for (int q = 0; q < 4; q++) acc[i][j][q] = 0.f;

    auto load_stage = [&](int c, int st) {
        const int col = c * 64;       // element offset of 64-K chunk
        const uint32_t sA = smem_u + st * STAGE_BYTES;
        const uint32_t sB = sA + 16384;
        #pragma unroll
        for (int l = 0; l < 8; l++) {
            int r = lr + l * 16;
            CP_ASYNC16(sA + (uint32_t)(r * 128) + lsw,
                       (const char*)(Abase + (size_t)r * rstride + col) + lch * 16);
        }
        #pragma unroll
        for (int l = 0; l < 8; l++) {
            int r = lr + l * 16;
            CP_ASYNC16(sB + (uint32_t)(r * 128) + lsw,
                       (const char*)(Bbase + (size_t)r * rstride + col) + lch * 16);
        }
    };

    const int rowA0 = wm * 64 + (lane & 15);
    const int kbA = (lane >> 4) * 8;
    const int g = lane >> 3;
    const int rowB0 = wn * 64 + ((g >> 1) << 3) + (lane & 7);
    const int kbB = (g & 1) * 8;

    auto compute_stage = [&](int st) {
        const uint32_t sA = smem_u + st * STAGE_BYTES;
        const uint32_t sB = sA + 16384;
        #pragma unroll
        for (int ks = 0; ks < 4; ks++) {
            uint32_t af[4][4], bf[4][4];
            #pragma unroll
            for (int mf = 0; mf < 4; mf++) {
                int row = rowA0 + mf * 16;
                uint32_t koff = (uint32_t)((ks * 16 + kbA) * 2) ^ (uint32_t)((row & 7) << 4);
                LDSM_X4(af[mf], sA + (uint32_t)(row * 128) + koff);
            }
            #pragma unroll
            for (int ng = 0; ng < 4; ng++) {
                int row = rowB0 + ng * 16;
                uint32_t koff = (uint32_t)((ks * 16 + kbB) * 2) ^ (uint32_t)((row & 7) << 4);
                LDSM_X4(bf[ng], sB + (uint32_t)(row * 128) + koff);
            }
            #pragma unroll
            for (int ng = 0; ng < 4; ng++)
                #pragma unroll
                for (int mf = 0; mf < 4; mf++) {
                    MMAH16816(acc[mf][2 * ng],     af[mf], bf[ng][0], bf[ng][1]);
                    MMAH16816(acc[mf][2 * ng + 1], af[mf], bf[ng][2], bf[ng][3]);
                }
        }
    };

    load_stage(0, 0); CP_COMMIT();
    load_stage(1, 1); CP_COMMIT();
    for (int c = 0; c < NCH; c++) {
        CP_WAIT1();
        __syncthreads();
        if (c + 2 < NCH) load_stage(c + 2, (c + 2) % 3);
        CP_COMMIT();
        compute_stage(c % 3);
    }

    // ---------------- epilogue --------------------------------------------
    const float* bias = bias_all + (size_t)e * Nd;
    const int rbase = m0 + wm * 64 + (lane >> 2);
    const int cbase = n0 + wn * 64 + (lane & 3) * 2;

    #pragma unroll
    for (int mf = 0; mf < 4; mf++) {
        #pragma unroll
        for (int cp = 0; cp < 2; cp++) {
            int row = rbase + mf * 16 + cp * 8;
            if (row >= cnt) continue;
            if (LAYER == 1) {
                __half* orow = g_A2 + ((size_t)e * EMAX + row) * HDIM;
                #pragma unroll
                for (int nf = 0; nf < 8; nf++) {
                    int col = cbase + nf * 8;
                    float v0 = gelu_exact(acc[mf][nf][2 * cp]     + bias[col]);
                    float v1 = gelu_exact(acc[mf][nf][2 * cp + 1] + bias[col + 1]);
                    *(uint32_t*)&orow[col] = pack_h2(v0, v1);
                }
            } else {
                int slot = g_slots[e * NTOK + row];
                float* orow = g_y + (size_t)slot * ODIM;
                #pragma unroll
                for (int nf = 0; nf < 8; nf++) {
                    int col = cbase + nf * 8;
                    float v0 = gelu_exact(acc[mf][nf][2 * cp]     + bias[col]);
                    float v1 = gelu_exact(acc[mf][nf][2 * cp + 1] + bias[col + 1]);
                    *(float2*)&orow[col] = make_float2(v0, v1);
                }
            }
        }
    }
}

// ---------------- kernel 6: combine + mask ---------------------------------
__global__ __launch_bounds__(256)
void combine_kernel(const float* __restrict__ mask, float* __restrict__ out)
{
    const int n = blockIdx.x;
    const int tid = threadIdx.x;
    const float m  = mask[n];
    const float p0 = g_prob[2 * n] * m;
    const float p1 = g_prob[2 * n + 1] * m;
    const float* y0 = g_y + (size_t)(2 * n) * ODIM;
    const float* y1 = y0 + ODIM;
    float* o = out + (size_t)n * ODIM;
    for (int c = tid; c < ODIM; c += 256)
        o[c] = p0 * y0[c] + p1 * y1[c];
}

// ---------------- launch ----------------------------------------------------
extern "C" void kernel_launch(void* const* d_in, const int* in_sizes, int n_in,
                              void* d_out, int out_size)
{
    const float* x     = (const float*)d_in[0];
    const float* mask  = (const float*)d_in[1];
    const float* gamma = (const float*)d_in[2];
    const float* beta  = (const float*)d_in[3];
    const float* rw    = (const float*)d_in[4];
    const float* w1    = (const float*)d_in[5];
    const float* b1    = (const float*)d_in[6];
    const float* w2    = (const float*)d_in[7];
    const float* b2    = (const float*)d_in[8];
    float* out = (float*)d_out;

    const int TBO = NTOK * ODIM;
    const int write_logits = (out_size >= TBO + NTOK * NEXP) ? 1 : 0;
    const int DSMEM = 98304;   // 3 stages x (16K A + 16K B)

    static int attr_done = 0;
    if (!attr_done) {
        cudaFuncSetAttribute(mma_gemm<1>, cudaFuncAttributeMaxDynamicSharedMemorySize, DSMEM);
        cudaFuncSetAttribute(mma_gemm<2>, cudaFuncAttributeMaxDynamicSharedMemorySize, DSMEM);
        attr_done = 1;
    }

    zero_kernel<<<1, 32>>>();
    ln_router_kernel<<<NTOK, 256>>>(x, gamma, beta, rw, out + TBO, write_logits);
    pack1_kernel<<<dim3(EMAX / 128, NEXP), 256>>>();
    wcvt_kernel<1><<<dim3(DDIM / 32, HDIM / 32, NEXP), 256>>>(w1);
    wcvt_kernel<2><<<dim3(HDIM / 32, ODIM / 32, NEXP), 256>>>(w2);
    mma_gemm<1><<<dim3(EMAX / 128, HDIM / 128, NEXP), 128, DSMEM>>>(b1);
    mma_gemm<2><<<dim3(EMAX / 128, ODIM / 128, NEXP), 128, DSMEM>>>(b2);
    combine_kernel<<<NTOK, 256>>>(mask, out);
}

// round 13
// speedup vs baseline: 1.1350x; 1.1350x over previous
#include <cuda_runtime.h>
#include <cuda_fp16.h>
#include <math.h>
#include <cstdint>

#define NTOK 4096      // T*B
#define DDIM 1024
#define HDIM 2048
#define ODIM 1024
#define NEXP 8
#define EMAX 4096      // max tokens per expert

// fp16 panels: A [E][EMAX][Kd] (row-major K), B [E][Nd][Kd] (N rows, K contig).

// ---------------- scratch (device globals; no allocation allowed) ----------
__device__ __half g_xnh[(size_t)NTOK * DDIM];                        // 8 MB fp16 LN output
__device__ float g_y[(size_t)2 * NTOK * ODIM];                       // 32 MB
__device__ int   g_cnt[NEXP];
__device__ int   g_slots[NEXP * NTOK];
__device__ float g_prob[2 * NTOK];
__device__ __half g_A1[(size_t)NEXP * EMAX * DDIM];                  // 67 MB
__device__ __half g_A2[(size_t)NEXP * EMAX * HDIM];                  // 134 MB
__device__ __half g_B1[(size_t)NEXP * HDIM * DDIM];                  // 33.5 MB
__device__ __half g_B2[(size_t)NEXP * ODIM * HDIM];                  // 33.5 MB

// ---------------- PTX helpers ----------------------------------------------
__device__ __forceinline__ uint32_t smem_to_u32(const void* p) {
    uint32_t a;
    asm("{ .reg .u64 t; cvta.to.shared.u64 t, %1; cvt.u32.u64 %0, t; }" : "=r"(a) : "l"(p));
    return a;
}
#define CP_ASYNC16(saddr, gptr) \
    asm volatile("cp.async.cg.shared.global [%0], [%1], 16;" :: "r"(saddr), "l"(gptr))
#define CP_COMMIT() asm volatile("cp.async.commit_group;" ::: "memory")
#define CP_WAIT1()  asm volatile("cp.async.wait_group 1;" ::: "memory")
#define LDSM_X4(R, addr) \
    asm volatile("ldmatrix.sync.aligned.m8n8.x4.shared.b16 {%0,%1,%2,%3}, [%4];" \
                 : "=r"((R)[0]), "=r"((R)[1]), "=r"((R)[2]), "=r"((R)[3]) : "r"(addr))
#define MMAH16816(D, A, B0, B1) \
    asm volatile("mma.sync.aligned.m16n8k16.row.col.f32.f16.f16.f32 " \
        "{%0,%1,%2,%3}, {%4,%5,%6,%7}, {%8,%9}, {%0,%1,%2,%3};" \
        : "+f"((D)[0]), "+f"((D)[1]), "+f"((D)[2]), "+f"((D)[3]) \
        : "r"((A)[0]), "r"((A)[1]), "r"((A)[2]), "r"((A)[3]), "r"(B0), "r"(B1))

__device__ __forceinline__ float gelu_exact(float v) {
    return 0.5f * v * (1.0f + erff(v * 0.70710678118654752440f));
}
__device__ __forceinline__ uint32_t pack_h2(float a, float b) {
    __half2 h = __floats2half2_rn(a, b);
    return *(uint32_t*)&h;
}

// ---------------- kernel 0: zero counters ----------------------------------
__global__ void zero_kernel() {
    if (threadIdx.x < NEXP) g_cnt[threadIdx.x] = 0;
}

// ---------------- kernel 1: LN + router + top2 + scatter -------------------
__global__ __launch_bounds__(256)
void ln_router_kernel(const float* __restrict__ x,
                      const float* __restrict__ gamma,
                      const float* __restrict__ beta,
                      const float* __restrict__ rw,
                      float* __restrict__ logits_out,
                      int write_logits)
{
    const int n = blockIdx.x;
    const int tid = threadIdx.x;
    __shared__ float sx[DDIM];
    __shared__ float red[256];
    __shared__ float sstat[2];
    __shared__ float lg[NEXP];

    const float* xr = x + (size_t)n * DDIM;
    float s = 0.f;
    for (int i = tid; i < DDIM; i += 256) { float v = xr[i]; sx[i] = v; s += v; }
    red[tid] = s; __syncthreads();
    for (int st = 128; st > 0; st >>= 1) { if (tid < st) red[tid] += red[tid + st]; __syncthreads(); }
    if (tid == 0) sstat[0] = red[0] * (1.0f / DDIM);
    __syncthreads();
    const float mu = sstat[0];
    float s2 = 0.f;
    for (int i = tid; i < DDIM; i += 256) { float v = sx[i] - mu; s2 += v * v; }
    red[tid] = s2; __syncthreads();
    for (int st = 128; st > 0; st >>= 1) { if (tid < st) red[tid] += red[tid + st]; __syncthreads(); }
    if (tid == 0) sstat[1] = rsqrtf(red[0] * (1.0f / DDIM) + 1e-5f);
    __syncthreads();
    const float rstd = sstat[1];
    for (int i = tid; i < DDIM; i += 256) {
        float v = (sx[i] - mu) * rstd * gamma[i] + beta[i];
        sx[i] = v;
    }
    __syncthreads();
    // fp16 write: 4 elems / thread as one uint2 (coalesced 8B)
    {
        int i = tid * 4;
        uint2 hp = make_uint2(pack_h2(sx[i], sx[i + 1]), pack_h2(sx[i + 2], sx[i + 3]));
        *(uint2*)&g_xnh[(size_t)n * DDIM + i] = hp;
    }

    const int w = tid >> 5, lane = tid & 31;
    {
        const float* r = rw + w * DDIM;
        float p = 0.f;
        for (int i = lane; i < DDIM; i += 32) p += sx[i] * r[i];
        #pragma unroll
        for (int o = 16; o > 0; o >>= 1) p += __shfl_down_sync(0xffffffffu, p, o);
        if (lane == 0) lg[w] = p;
    }
    __syncthreads();

    if (tid == 0) {
        if (write_logits) {
            #pragma unroll
            for (int e = 0; e < NEXP; e++) logits_out[(size_t)n * NEXP + e] = lg[e];
        }
        int i0 = 0;
        #pragma unroll
        for (int e = 1; e < NEXP; e++) if (lg[e] > lg[i0]) i0 = e;
        int i1 = (i0 == 0) ? 1 : 0;
        #pragma unroll
        for (int e = 0; e < NEXP; e++) if (e != i0 && lg[e] > lg[i1]) i1 = e;
        float q = expf(lg[i1] - lg[i0]);
        float inv = 1.0f / (1.0f + q);
        g_prob[2 * n]     = inv;
        g_prob[2 * n + 1] = q * inv;
        int p0 = atomicAdd(&g_cnt[i0], 1); g_slots[i0 * NTOK + p0] = 2 * n;
        int p1 = atomicAdd(&g_cnt[i1], 1); g_slots[i1 * NTOK + p1] = 2 * n + 1;
    }
}

// ---------------- kernel 2: gather tokens into per-expert A1 (uint4 copy) --
__global__ __launch_bounds__(256)
void pack1_kernel()
{
    const int e = blockIdx.y;
    const int m0 = blockIdx.x * 128;
    const int cnt = g_cnt[e];
    if (m0 >= cnt) return;
    const int tid = threadIdx.x;
    __half* outp = g_A1 + ((size_t)e * EMAX) * DDIM;
    // 128 rows x 128 uint4 (2KB/row); 64 iterations of 256 threads
    for (int idx = tid; idx < 128 * 128; idx += 256) {
        int r = idx >> 7;
        int c8 = idx & 127;            // uint4 index within row (8 halves)
        int row = m0 + r;
        if (row >= cnt) continue;
        int token = g_slots[e * NTOK + row] >> 1;
        uint4 v = ((const uint4*)g_xnh)[(size_t)token * 128 + c8];
        ((uint4*)outp)[(size_t)row * 128 + c8] = v;
    }
}

// ---------------- kernel 3: weight transpose to fp16 (64x64 tiles) ---------
// W [E][Kd][Nd] (fp32) -> B [E][Nd][Kd] (fp16)
template<int LAYER>
__global__ __launch_bounds__(256)
void wcvt_kernel(const float* __restrict__ W)
{
    constexpr int Kd = (LAYER == 1) ? DDIM : HDIM;
    constexpr int Nd = (LAYER == 1) ? HDIM : ODIM;
    __half* Bout = (LAYER == 1) ? g_B1 : g_B2;
    const int e = blockIdx.z;
    const int d0 = blockIdx.x * 64;   // K base
    const int h0 = blockIdx.y * 64;   // N base
    __shared__ float st[64][65];
    const int tid = threadIdx.x;
    // load 64x64 floats: 1024 float4s, 4 per thread (coalesced along N)
    #pragma unroll
    for (int p = 0; p < 4; p++) {
        int f = tid + p * 256;
        int dl = f >> 4, cq = f & 15;
        float4 v = *(const float4*)(W + ((size_t)e * Kd + d0 + dl) * Nd + h0 + cq * 4);
        st[dl][cq * 4 + 0] = v.x; st[dl][cq * 4 + 1] = v.y;
        st[dl][cq * 4 + 2] = v.z; st[dl][cq * 4 + 3] = v.w;
    }
    __syncthreads();
    // store 64 N-rows x 64 K as fp16: 512 uint4s, 2 per thread (16B stores)
    #pragma unroll
    for (int p = 0; p < 2; p++) {
        int idx = tid + p * 256;
        int n = idx >> 3, ks = (idx & 7) * 8;
        uint4 pk;
        pk.x = pack_h2(st[ks + 0][n], st[ks + 1][n]);
        pk.y = pack_h2(st[ks + 2][n], st[ks + 3][n]);
        pk.z = pack_h2(st[ks + 4][n], st[ks + 5][n]);
        pk.w = pack_h2(st[ks + 6][n], st[ks + 7][n]);
        *(uint4*)&Bout[((size_t)e * Nd + h0 + n) * Kd + d0 + ks] = pk;
    }
}

// ---------------- kernels 4/5: grouped fp16 GEMM via mma.sync --------------
// CTA tile 128x128, 8 warps (4x2), warp tile 32x64. K-chunk = 64; 3-stage
// cp.async. (R11 configuration -- the known-best GEMM shape.)
template<int LAYER>
__global__ __launch_bounds__(256, 2)
void mma_gemm(const float* __restrict__ bias_all)
{
    constexpr int Kd = (LAYER == 1) ? DDIM : HDIM;
    constexpr int Nd = (LAYER == 1) ? HDIM : ODIM;
    constexpr int NCH = Kd / 64;
    constexpr int STAGE_BYTES = 32768;   // A 16K + B 16K
    const __half* __restrict__ Aall = (LAYER == 1) ? g_A1 : g_A2;
    const __half* __restrict__ Ball = (LAYER == 1) ? g_B1 : g_B2;

    const int e = blockIdx.z;
    const int cnt = g_cnt[e];
    const int m0 = blockIdx.x * 128;
    if (m0 >= cnt) return;
    const int n0 = blockIdx.y * 128;

    extern __shared__ __align__(1024) char smem[];
    const uint32_t smem_u = smem_to_u32(smem);

    const int tid = threadIdx.x;
    const int lane = tid & 31;
    const int wid = tid >> 5;
    const int wm = wid >> 1;
    const int wn = wid & 1;

    const size_t rstride = Kd;   // elements
    const __half* Abase = Aall + ((size_t)e * EMAX + m0) * rstride;
    const __half* Bbase = Ball + ((size_t)e * Nd + n0) * rstride;

    const int lr = tid >> 3;          // 4 rows/thread, stride 32
    const int lch = tid & 7;          // 16B chunk in 128B row
    const uint32_t lsw = (uint32_t)(lch * 16) ^ (uint32_t)((lr & 7) << 4);

    float acc[2][8][4];
    #pragma unroll
    for (int i = 0; i < 2; i++)
        #pragma unroll
        for (int j = 0; j < 8; j++)
            #pragma unroll
            for (int q = 0; q < 4; q++) acc[i][j][q] = 0.f;

    auto load_stage = [&](int c, int st) {
        const int col = c * 64;       // element offset of 64-K chunk
        const uint32_t sA = smem_u + st * STAGE_BYTES;
        const uint32_t sB = sA + 16384;
        #pragma unroll
        for (int l = 0; l < 4; l++) {
            int r = lr + l * 32;
            CP_ASYNC16(sA + (uint32_t)(r * 128) + lsw,
                       (const char*)(Abase + (size_t)r * rstride + col) + lch * 16);
        }
        #pragma unroll
        for (int l = 0; l < 4; l++) {
            int r = lr + l * 32;
            CP_ASYNC16(sB + (uint32_t)(r * 128) + lsw,
                       (const char*)(Bbase + (size_t)r * rstride + col) + lch * 16);
        }
    };

    const int rowA0 = wm * 32 + (lane & 15);
    const int kbA = (lane >> 4) * 8;
    const int g = lane >> 3;
    const int rowB0 = wn * 64 + ((g >> 1) << 3) + (lane & 7);
    const int kbB = (g & 1) * 8;

    auto compute_stage = [&](int st) {
        const uint32_t sA = smem_u + st * STAGE_BYTES;
        const uint32_t sB = sA + 16384;
        #pragma unroll
        for (int ks = 0; ks < 4; ks++) {
            uint32_t af[2][4], bf[4][4];
            #pragma unroll
            for (int mf = 0; mf < 2; mf++) {
                int row = rowA0 + mf * 16;
                uint32_t koff = (uint32_t)((ks * 16 + kbA) * 2) ^ (uint32_t)((row & 7) << 4);
                LDSM_X4(af[mf], sA + (uint32_t)(row * 128) + koff);
            }
            #pragma unroll
            for (int ng = 0; ng < 4; ng++) {
                int row = rowB0 + ng * 16;
                uint32_t koff = (uint32_t)((ks * 16 + kbB) * 2) ^ (uint32_t)((row & 7) << 4);
                LDSM_X4(bf[ng], sB + (uint32_t)(row * 128) + koff);
            }
            #pragma unroll
            for (int ng = 0; ng < 4; ng++)
                #pragma unroll
                for (int mf = 0; mf < 2; mf++) {
                    MMAH16816(acc[mf][2 * ng],     af[mf], bf[ng][0], bf[ng][1]);
                    MMAH16816(acc[mf][2 * ng + 1], af[mf], bf[ng][2], bf[ng][3]);
                }
        }
    };

    load_stage(0, 0); CP_COMMIT();
    load_stage(1, 1); CP_COMMIT();
    for (int c = 0; c < NCH; c++) {
        CP_WAIT1();
        __syncthreads();
        if (c + 2 < NCH) load_stage(c + 2, (c + 2) % 3);
        CP_COMMIT();
        compute_stage(c % 3);
    }

    // ---------------- epilogue --------------------------------------------
    const float* bias = bias_all + (size_t)e * Nd;
    const int rbase = m0 + wm * 32 + (lane >> 2);
    const int cbase = n0 + wn * 64 + (lane & 3) * 2;

    #pragma unroll
    for (int mf = 0; mf < 2; mf++) {
        #pragma unroll
        for (int cp = 0; cp < 2; cp++) {
            int row = rbase + mf * 16 + cp * 8;
            if (row >= cnt) continue;
            if (LAYER == 1) {
                __half* orow = g_A2 + ((size_t)e * EMAX + row) * HDIM;
                #pragma unroll
                for (int nf = 0; nf < 8; nf++) {
                    int col = cbase + nf * 8;
                    float v0 = gelu_exact(acc[mf][nf][2 * cp]     + bias[col]);
                    float v1 = gelu_exact(acc[mf][nf][2 * cp + 1] + bias[col + 1]);
                    *(uint32_t*)&orow[col] = pack_h2(v0, v1);
                }
            } else {
                int slot = g_slots[e * NTOK + row];
                float* orow = g_y + (size_t)slot * ODIM;
                #pragma unroll
                for (int nf = 0; nf < 8; nf++) {
                    int col = cbase + nf * 8;
                    float v0 = gelu_exact(acc[mf][nf][2 * cp]     + bias[col]);
                    float v1 = gelu_exact(acc[mf][nf][2 * cp + 1] + bias[col + 1]);
                    *(float2*)&orow[col] = make_float2(v0, v1);
                }
            }
        }
    }
}

// ---------------- kernel 6: combine + mask (float4) ------------------------
__global__ __launch_bounds__(256)
void combine_kernel(const float* __restrict__ mask, float* __restrict__ out)
{
    const int n = blockIdx.x;
    const int tid = threadIdx.x;
    const float m  = mask[n];
    const float p0 = g_prob[2 * n] * m;
    const float p1 = g_prob[2 * n + 1] * m;
    const float4* y0 = (const float4*)(g_y + (size_t)(2 * n) * ODIM);
    const float4* y1 = y0 + ODIM / 4;
    float4* o = (float4*)(out + (size_t)n * ODIM);
    {
        float4 a = y0[tid], b = y1[tid];
        o[tid] = make_float4(p0 * a.x + p1 * b.x, p0 * a.y + p1 * b.y,
                             p0 * a.z + p1 * b.z, p0 * a.w + p1 * b.w);
    }
}

// ---------------- launch ----------------------------------------------------
extern "C" void kernel_launch(void* const* d_in, const int* in_sizes, int n_in,
                              void* d_out, int out_size)
{
    const float* x     = (const float*)d_in[0];
    const float* mask  = (const float*)d_in[1];
    const float* gamma = (const float*)d_in[2];
    const float* beta  = (const float*)d_in[3];
    const float* rw    = (const float*)d_in[4];
    const float* w1    = (const float*)d_in[5];
    const float* b1    = (const float*)d_in[6];
    const float* w2    = (const float*)d_in[7];
    const float* b2    = (const float*)d_in[8];
    float* out = (float*)d_out;

    const int TBO = NTOK * ODIM;
    const int write_logits = (out_size >= TBO + NTOK * NEXP) ? 1 : 0;
    const int DSMEM = 98304;   // 3 stages x (16K A + 16K B)

    static int attr_done = 0;
    if (!attr_done) {
        cudaFuncSetAttribute(mma_gemm<1>, cudaFuncAttributeMaxDynamicSharedMemorySize, DSMEM);
        cudaFuncSetAttribute(mma_gemm<2>, cudaFuncAttributeMaxDynamicSharedMemorySize, DSMEM);
        attr_done = 1;
    }

    zero_kernel<<<1, 32>>>();
    ln_router_kernel<<<NTOK, 256>>>(x, gamma, beta, rw, out + TBO, write_logits);
    pack1_kernel<<<dim3(EMAX / 128, NEXP), 256>>>();
    wcvt_kernel<1><<<dim3(DDIM / 64, HDIM / 64, NEXP), 256>>>(w1);
    wcvt_kernel<2><<<dim3(HDIM / 64, ODIM / 64, NEXP), 256>>>(w2);
    mma_gemm<1><<<dim3(EMAX / 128, HDIM / 128, NEXP), 256, DSMEM>>>(b1);
    mma_gemm<2><<<dim3(EMAX / 128, ODIM / 128, NEXP), 256, DSMEM>>>(b2);
    combine_kernel<<<NTOK, 256>>>(mask, out);
}

// round 14
// speedup vs baseline: 1.1917x; 1.0500x over previous
#include <cuda_runtime.h>
#include <cuda_fp16.h>
#include <math.h>
#include <cstdint>

#define NTOK 4096      // T*B
#define DDIM 1024
#define HDIM 2048
#define ODIM 1024
#define NEXP 8
#define EMAX 4096      // max tokens per expert

// fp16 panels: A2 [E][EMAX][HDIM], B [E][Nd][Kd] (N rows, K contig).
// GEMM1 gathers its A rows directly from g_xnh via g_slots (no packed A1).

// ---------------- scratch (device globals; no allocation allowed) ----------
__device__ __half g_xnh[(size_t)NTOK * DDIM];                        // 8 MB fp16 LN output
__device__ int   g_cnt[NEXP];
__device__ int   g_slots[NEXP * NTOK];
__device__ float g_prob[2 * NTOK];
__device__ __half g_A2[(size_t)NEXP * EMAX * HDIM];                  // 134 MB
__device__ __half g_B1[(size_t)NEXP * HDIM * DDIM];                  // 33.5 MB
__device__ __half g_B2[(size_t)NEXP * ODIM * HDIM];                  // 33.5 MB

// ---------------- PTX helpers ----------------------------------------------
__device__ __forceinline__ uint32_t smem_to_u32(const void* p) {
    uint32_t a;
    asm("{ .reg .u64 t; cvta.to.shared.u64 t, %1; cvt.u32.u64 %0, t; }" : "=r"(a) : "l"(p));
    return a;
}
#define CP_ASYNC16(saddr, gptr) \
    asm volatile("cp.async.cg.shared.global [%0], [%1], 16;" :: "r"(saddr), "l"(gptr))
#define CP_COMMIT() asm volatile("cp.async.commit_group;" ::: "memory")
#define CP_WAIT1()  asm volatile("cp.async.wait_group 1;" ::: "memory")
#define LDSM_X4(R, addr) \
    asm volatile("ldmatrix.sync.aligned.m8n8.x4.shared.b16 {%0,%1,%2,%3}, [%4];" \
                 : "=r"((R)[0]), "=r"((R)[1]), "=r"((R)[2]), "=r"((R)[3]) : "r"(addr))
#define MMAH16816(D, A, B0, B1) \
    asm volatile("mma.sync.aligned.m16n8k16.row.col.f32.f16.f16.f32 " \
        "{%0,%1,%2,%3}, {%4,%5,%6,%7}, {%8,%9}, {%0,%1,%2,%3};" \
        : "+f"((D)[0]), "+f"((D)[1]), "+f"((D)[2]), "+f"((D)[3]) \
        : "r"((A)[0]), "r"((A)[1]), "r"((A)[2]), "r"((A)[3]), "r"(B0), "r"(B1))

__device__ __forceinline__ float gelu_exact(float v) {
    return 0.5f * v * (1.0f + erff(v * 0.70710678118654752440f));
}
__device__ __forceinline__ uint32_t pack_h2(float a, float b) {
    __half2 h = __floats2half2_rn(a, b);
    return *(uint32_t*)&h;
}

// ---------------- kernel 0: zero counters ----------------------------------
__global__ void zero_kernel() {
    if (threadIdx.x < NEXP) g_cnt[threadIdx.x] = 0;
}

// ---------------- kernel 0b: zero output region ----------------------------
__global__ __launch_bounds__(256)
void zero_out_kernel(float* __restrict__ out) {
    ((float4*)out)[blockIdx.x * 256 + threadIdx.x] =
        make_float4(0.f, 0.f, 0.f, 0.f);
}

// ---------------- kernel 1: LN + router + top2 + scatter -------------------
__global__ __launch_bounds__(256)
void ln_router_kernel(const float* __restrict__ x,
                      const float* __restrict__ gamma,
                      const float* __restrict__ beta,
                      const float* __restrict__ rw,
                      float* __restrict__ logits_out,
                      int write_logits)
{
    const int n = blockIdx.x;
    const int tid = threadIdx.x;
    __shared__ float sx[DDIM];
    __shared__ float red[256];
    __shared__ float sstat[2];
    __shared__ float lg[NEXP];

    const float* xr = x + (size_t)n * DDIM;
    float s = 0.f;
    for (int i = tid; i < DDIM; i += 256) { float v = xr[i]; sx[i] = v; s += v; }
    red[tid] = s; __syncthreads();
    for (int st = 128; st > 0; st >>= 1) { if (tid < st) red[tid] += red[tid + st]; __syncthreads(); }
    if (tid == 0) sstat[0] = red[0] * (1.0f / DDIM);
    __syncthreads();
    const float mu = sstat[0];
    float s2 = 0.f;
    for (int i = tid; i < DDIM; i += 256) { float v = sx[i] - mu; s2 += v * v; }
    red[tid] = s2; __syncthreads();
    for (int st = 128; st > 0; st >>= 1) { if (tid < st) red[tid] += red[tid + st]; __syncthreads(); }
    if (tid == 0) sstat[1] = rsqrtf(red[0] * (1.0f / DDIM) + 1e-5f);
    __syncthreads();
    const float rstd = sstat[1];
    for (int i = tid; i < DDIM; i += 256) {
        float v = (sx[i] - mu) * rstd * gamma[i] + beta[i];
        sx[i] = v;
    }
    __syncthreads();
    {
        int i = tid * 4;
        uint2 hp = make_uint2(pack_h2(sx[i], sx[i + 1]), pack_h2(sx[i + 2], sx[i + 3]));
        *(uint2*)&g_xnh[(size_t)n * DDIM + i] = hp;
    }

    const int w = tid >> 5, lane = tid & 31;
    {
        const float* r = rw + w * DDIM;
        float p = 0.f;
        for (int i = lane; i < DDIM; i += 32) p += sx[i] * r[i];
        #pragma unroll
        for (int o = 16; o > 0; o >>= 1) p += __shfl_down_sync(0xffffffffu, p, o);
        if (lane == 0) lg[w] = p;
    }
    __syncthreads();

    if (tid == 0) {
        if (write_logits) {
            #pragma unroll
            for (int e = 0; e < NEXP; e++) logits_out[(size_t)n * NEXP + e] = lg[e];
        }
        int i0 = 0;
        #pragma unroll
        for (int e = 1; e < NEXP; e++) if (lg[e] > lg[i0]) i0 = e;
        int i1 = (i0 == 0) ? 1 : 0;
        #pragma unroll
        for (int e = 0; e < NEXP; e++) if (e != i0 && lg[e] > lg[i1]) i1 = e;
        float q = expf(lg[i1] - lg[i0]);
        float inv = 1.0f / (1.0f + q);
        g_prob[2 * n]     = inv;
        g_prob[2 * n + 1] = q * inv;
        int p0 = atomicAdd(&g_cnt[i0], 1); g_slots[i0 * NTOK + p0] = 2 * n;
        int p1 = atomicAdd(&g_cnt[i1], 1); g_slots[i1 * NTOK + p1] = 2 * n + 1;
    }
}

// ---------------- kernel 3: weight transpose to fp16 (64x64 tiles) ---------
// W [E][Kd][Nd] (fp32) -> B [E][Nd][Kd] (fp16)
template<int LAYER>
__global__ __launch_bounds__(256)
void wcvt_kernel(const float* __restrict__ W)
{
    constexpr int Kd = (LAYER == 1) ? DDIM : HDIM;
    constexpr int Nd = (LAYER == 1) ? HDIM : ODIM;
    __half* Bout = (LAYER == 1) ? g_B1 : g_B2;
    const int e = blockIdx.z;
    const int d0 = blockIdx.x * 64;   // K base
    const int h0 = blockIdx.y * 64;   // N base
    __shared__ float st[64][65];
    const int tid = threadIdx.x;
    #pragma unroll
    for (int p = 0; p < 4; p++) {
        int f = tid + p * 256;
        int dl = f >> 4, cq = f & 15;
        float4 v = *(const float4*)(W + ((size_t)e * Kd + d0 + dl) * Nd + h0 + cq * 4);
        st[dl][cq * 4 + 0] = v.x; st[dl][cq * 4 + 1] = v.y;
        st[dl][cq * 4 + 2] = v.z; st[dl][cq * 4 + 3] = v.w;
    }
    __syncthreads();
    #pragma unroll
    for (int p = 0; p < 2; p++) {
        int idx = tid + p * 256;
        int n = idx >> 3, ks = (idx & 7) * 8;
        uint4 pk;
        pk.x = pack_h2(st[ks + 0][n], st[ks + 1][n]);
        pk.y = pack_h2(st[ks + 2][n], st[ks + 3][n]);
        pk.z = pack_h2(st[ks + 4][n], st[ks + 5][n]);
        pk.w = pack_h2(st[ks + 6][n], st[ks + 7][n]);
        *(uint4*)&Bout[((size_t)e * Nd + h0 + n) * Kd + d0 + ks] = pk;
    }
}

// ---------------- kernels 4/5: grouped fp16 GEMM via mma.sync --------------
// CTA tile 128x128, 8 warps (4x2), warp tile 32x64. K-chunk = 64; 3-stage
// cp.async. LAYER1 gathers A rows from g_xnh via smem pointer table; its
// epilogue packs GELU to g_A2. LAYER2 epilogue atomic-adds weighted GELU
// into d_out (each element exactly 2 contributions -> deterministic).
template<int LAYER>
__global__ __launch_bounds__(256, 2)
void mma_gemm(const float* __restrict__ bias_all,
              const float* __restrict__ mask,
              float* __restrict__ outp)
{
    constexpr int Kd = (LAYER == 1) ? DDIM : HDIM;
    constexpr int Nd = (LAYER == 1) ? HDIM : ODIM;
    constexpr int NCH = Kd / 64;
    constexpr int STAGE_BYTES = 32768;   // A 16K + B 16K
    const __half* __restrict__ Ball = (LAYER == 1) ? g_B1 : g_B2;

    const int e = blockIdx.z;
    const int cnt = g_cnt[e];
    const int m0 = blockIdx.x * 128;
    if (m0 >= cnt) return;
    const int n0 = blockIdx.y * 128;

    extern __shared__ __align__(1024) char smem[];
    const uint32_t smem_u = smem_to_u32(smem);
    __shared__ const __half* sArow[128];

    const int tid = threadIdx.x;
    const int lane = tid & 31;
    const int wid = tid >> 5;
    const int wm = wid >> 1;
    const int wn = wid & 1;

    // A row base pointers (gathered for layer 1, contiguous for layer 2)
    if (tid < 128) {
        int r = m0 + tid;
        if (LAYER == 1) {
            int slot = (r < cnt) ? g_slots[e * NTOK + r] : g_slots[e * NTOK];
            sArow[tid] = g_xnh + (size_t)(slot >> 1) * DDIM;
        } else {
            sArow[tid] = g_A2 + ((size_t)e * EMAX + r) * HDIM;
        }
    }

    const size_t rstride = Kd;   // elements
    const __half* Bbase = Ball + ((size_t)e * Nd + n0) * rstride;

    const int lr = tid >> 3;          // 4 rows/thread, stride 32
    const int lch = tid & 7;          // 16B chunk in 128B row
    const uint32_t lsw = (uint32_t)(lch * 16) ^ (uint32_t)((lr & 7) << 4);

    float acc[2][8][4];
    #pragma unroll
    for (int i = 0; i < 2; i++)
        #pragma unroll
        for (int j = 0; j < 8; j++)
            #pragma unroll
            for (int q = 0; q < 4; q++) acc[i][j][q] = 0.f;

    __syncthreads();   // sArow visible before first load

    auto load_stage = [&](int c, int st) {
        const int col = c * 64;       // element offset of 64-K chunk
        const uint32_t sA = smem_u + st * STAGE_BYTES;
        const uint32_t sB = sA + 16384;
        #pragma unroll
        for (int l = 0; l < 4; l++) {
            int r = lr + l * 32;
            CP_ASYNC16(sA + (uint32_t)(r * 128) + lsw,
                       (const char*)(sArow[r] + col) + lch * 16);
        }
        #pragma unroll
        for (int l = 0; l < 4; l++) {
            int r = lr + l * 32;
            CP_ASYNC16(sB + (uint32_t)(r * 128) + lsw,
                       (const char*)(Bbase + (size_t)r * rstride + col) + lch * 16);
        }
    };

    const int rowA0 = wm * 32 + (lane & 15);
    const int kbA = (lane >> 4) * 8;
    const int g = lane >> 3;
    const int rowB0 = wn * 64 + ((g >> 1) << 3) + (lane & 7);
    const int kbB = (g & 1) * 8;

    auto compute_stage = [&](int st) {
        const uint32_t sA = smem_u + st * STAGE_BYTES;
        const uint32_t sB = sA + 16384;
        #pragma unroll
        for (int ks = 0; ks < 4; ks++) {
            uint32_t af[2][4], bf[4][4];
            #pragma unroll
            for (int mf = 0; mf < 2; mf++) {
                int row = rowA0 + mf * 16;
                uint32_t koff = (uint32_t)((ks * 16 + kbA) * 2) ^ (uint32_t)((row & 7) << 4);
                LDSM_X4(af[mf], sA + (uint32_t)(row * 128) + koff);
            }
            #pragma unroll
            for (int ng = 0; ng < 4; ng++) {
                int row = rowB0 + ng * 16;
                uint32_t koff = (uint32_t)((ks * 16 + kbB) * 2) ^ (uint32_t)((row & 7) << 4);
                LDSM_X4(bf[ng], sB + (uint32_t)(row * 128) + koff);
            }
            #pragma unroll
            for (int ng = 0; ng < 4; ng++)
                #pragma unroll
                for (int mf = 0; mf < 2; mf++) {
                    MMAH16816(acc[mf][2 * ng],     af[mf], bf[ng][0], bf[ng][1]);
                    MMAH16816(acc[mf][2 * ng + 1], af[mf], bf[ng][2], bf[ng][3]);
                }
        }
    };

    load_stage(0, 0); CP_COMMIT();
    load_stage(1, 1); CP_COMMIT();
    for (int c = 0; c < NCH; c++) {
        CP_WAIT1();
        __syncthreads();
        if (c + 2 < NCH) load_stage(c + 2, (c + 2) % 3);
        CP_COMMIT();
        compute_stage(c % 3);
    }

    // ---------------- epilogue --------------------------------------------
    const float* bias = bias_all + (size_t)e * Nd;
    const int rbase = m0 + wm * 32 + (lane >> 2);
    const int cbase = n0 + wn * 64 + (lane & 3) * 2;

    #pragma unroll
    for (int mf = 0; mf < 2; mf++) {
        #pragma unroll
        for (int cp = 0; cp < 2; cp++) {
            int row = rbase + mf * 16 + cp * 8;
            if (row >= cnt) continue;
            if (LAYER == 1) {
                __half* orow = g_A2 + ((size_t)e * EMAX + row) * HDIM;
                #pragma unroll
                for (int nf = 0; nf < 8; nf++) {
                    int col = cbase + nf * 8;
                    float v0 = gelu_exact(acc[mf][nf][2 * cp]     + bias[col]);
                    float v1 = gelu_exact(acc[mf][nf][2 * cp + 1] + bias[col + 1]);
                    *(uint32_t*)&orow[col] = pack_h2(v0, v1);
                }
            } else {
                int slot = g_slots[e * NTOK + row];
                int token = slot >> 1;
                float p = g_prob[slot] * mask[token];
                float* orow = outp + (size_t)token * ODIM;
                #pragma unroll
                for (int nf = 0; nf < 8; nf++) {
                    int col = cbase + nf * 8;
                    float v0 = gelu_exact(acc[mf][nf][2 * cp]     + bias[col]);
                    float v1 = gelu_exact(acc[mf][nf][2 * cp + 1] + bias[col + 1]);
                    atomicAdd(&orow[col],     p * v0);
                    atomicAdd(&orow[col + 1], p * v1);
                }
            }
        }
    }
}

// ---------------- launch ----------------------------------------------------
extern "C" void kernel_launch(void* const* d_in, const int* in_sizes, int n_in,
                              void* d_out, int out_size)
{
    const float* x     = (const float*)d_in[0];
    const float* mask  = (const float*)d_in[1];
    const float* gamma = (const float*)d_in[2];
    const float* beta  = (const float*)d_in[3];
    const float* rw    = (const float*)d_in[4];
    const float* w1    = (const float*)d_in[5];
    const float* b1    = (const float*)d_in[6];
    const float* w2    = (const float*)d_in[7];
    const float* b2    = (const float*)d_in[8];
    float* out = (float*)d_out;

    const int TBO = NTOK * ODIM;
    const int write_logits = (out_size >= TBO + NTOK * NEXP) ? 1 : 0;
    const int DSMEM = 98304;   // 3 stages x (16K A + 16K B)

    static int attr_done = 0;
    if (!attr_done) {
        cudaFuncSetAttribute(mma_gemm<1>, cudaFuncAttributeMaxDynamicSharedMemorySize, DSMEM);
        cudaFuncSetAttribute(mma_gemm<2>, cudaFuncAttributeMaxDynamicSharedMemorySize, DSMEM);
        attr_done = 1;
    }

    zero_kernel<<<1, 32>>>();
    zero_out_kernel<<<TBO / 1024, 256>>>(out);
    ln_router_kernel<<<NTOK, 256>>>(x, gamma, beta, rw, out + TBO, write_logits);
    wcvt_kernel<1><<<dim3(DDIM / 64, HDIM / 64, NEXP), 256>>>(w1);
    wcvt_kernel<2><<<dim3(HDIM / 64, ODIM / 64, NEXP), 256>>>(w2);
    mma_gemm<1><<<dim3(EMAX / 128, HDIM / 128, NEXP), 256, DSMEM>>>(b1, mask, nullptr);
    mma_gemm<2><<<dim3(EMAX / 128, ODIM / 128, NEXP), 256, DSMEM>>>(b2, mask, out);
}

// round 16
// speedup vs baseline: 1.2435x; 1.0435x over previous
#include <cuda_runtime.h>
#include <cuda_fp16.h>
#include <math.h>
#include <cstdint>

#define NTOK 4096      // T*B
#define DDIM 1024
#define HDIM 2048
#define ODIM 1024
#define NEXP 8
#define EMAX 4096      // max tokens per expert

// B panels stay in native [E][Kd][Nd] fp16 layout (no transpose); the GEMM
// loads B fragments with ldmatrix.trans. A2 [E][EMAX][HDIM] fp16.

// ---------------- scratch (device globals; no allocation allowed) ----------
__device__ __half g_xnh[(size_t)NTOK * DDIM];                        // 8 MB fp16 LN output
__device__ int   g_cnt[NEXP];
__device__ int   g_slots[NEXP * NTOK];
__device__ float g_prob[2 * NTOK];
__device__ __half g_A2[(size_t)NEXP * EMAX * HDIM];                  // 134 MB
__device__ __half g_B1[(size_t)NEXP * DDIM * HDIM];                  // 33.5 MB [K][N]
__device__ __half g_B2[(size_t)NEXP * HDIM * ODIM];                  // 33.5 MB [K][N]

// ---------------- PTX helpers ----------------------------------------------
__device__ __forceinline__ uint32_t smem_to_u32(const void* p) {
    uint32_t a;
    asm("{ .reg .u64 t; cvta.to.shared.u64 t, %1; cvt.u32.u64 %0, t; }" : "=r"(a) : "l"(p));
    return a;
}
#define CP_ASYNC16(saddr, gptr) \
    asm volatile("cp.async.cg.shared.global [%0], [%1], 16;" :: "r"(saddr), "l"(gptr))
#define CP_COMMIT() asm volatile("cp.async.commit_group;" ::: "memory")
#define CP_WAIT1()  asm volatile("cp.async.wait_group 1;" ::: "memory")
#define LDSM_X4(R, addr) \
    asm volatile("ldmatrix.sync.aligned.m8n8.x4.shared.b16 {%0,%1,%2,%3}, [%4];" \
                 : "=r"((R)[0]), "=r"((R)[1]), "=r"((R)[2]), "=r"((R)[3]) : "r"(addr))
#define LDSM_X4_T(R, addr) \
    asm volatile("ldmatrix.sync.aligned.m8n8.x4.trans.shared.b16 {%0,%1,%2,%3}, [%4];" \
                 : "=r"((R)[0]), "=r"((R)[1]), "=r"((R)[2]), "=r"((R)[3]) : "r"(addr))
#define MMAH16816(D, A, B0, B1) \
    asm volatile("mma.sync.aligned.m16n8k16.row.col.f32.f16.f16.f32 " \
        "{%0,%1,%2,%3}, {%4,%5,%6,%7}, {%8,%9}, {%0,%1,%2,%3};" \
        : "+f"((D)[0]), "+f"((D)[1]), "+f"((D)[2]), "+f"((D)[3]) \
        : "r"((A)[0]), "r"((A)[1]), "r"((A)[2]), "r"((A)[3]), "r"(B0), "r"(B1))

__device__ __forceinline__ float gelu_exact(float v) {
    return 0.5f * v * (1.0f + erff(v * 0.70710678118654752440f));
}
__device__ __forceinline__ uint32_t pack_h2(float a, float b) {
    __half2 h = __floats2half2_rn(a, b);
    return *(uint32_t*)&h;
}

// ---------------- kernel 0: zero output + counters -------------------------
__global__ __launch_bounds__(256)
void zero_out_kernel(float* __restrict__ out) {
    if (blockIdx.x == 0 && threadIdx.x < NEXP) g_cnt[threadIdx.x] = 0;
    ((float4*)out)[(size_t)blockIdx.x * 256 + threadIdx.x] =
        make_float4(0.f, 0.f, 0.f, 0.f);
}

// ---------------- kernel 1: LN + router + top2 (warp-per-token) ------------
__global__ __launch_bounds__(256)
void ln_router_kernel(const float* __restrict__ x,
                      const float* __restrict__ gamma,
                      const float* __restrict__ beta,
                      const float* __restrict__ rw,
                      float* __restrict__ logits_out,
                      int write_logits)
{
    const int warp = threadIdx.x >> 5, lane = threadIdx.x & 31;
    const int n = blockIdx.x * 8 + warp;
    const float4* xr = (const float4*)(x + (size_t)n * DDIM);
    float4 v[8];
    float s = 0.f;
    #pragma unroll
    for (int i = 0; i < 8; i++) {
        v[i] = xr[i * 32 + lane];
        s += (v[i].x + v[i].y) + (v[i].z + v[i].w);
    }
    #pragma unroll
    for (int o = 16; o; o >>= 1) s += __shfl_xor_sync(0xffffffffu, s, o);
    const float mu = s * (1.f / DDIM);
    float s2 = 0.f;
    #pragma unroll
    for (int i = 0; i < 8; i++) {
        float a = v[i].x - mu, b = v[i].y - mu, c = v[i].z - mu, d = v[i].w - mu;
        s2 += (a * a + b * b) + (c * c + d * d);
    }
    #pragma unroll
    for (int o = 16; o; o >>= 1) s2 += __shfl_xor_sync(0xffffffffu, s2, o);
    const float rstd = rsqrtf(s2 * (1.f / DDIM) + 1e-5f);

    #pragma unroll
    for (int i = 0; i < 8; i++) {
        float4 g4 = ((const float4*)gamma)[i * 32 + lane];
        float4 b4 = ((const float4*)beta)[i * 32 + lane];
        v[i].x = (v[i].x - mu) * rstd * g4.x + b4.x;
        v[i].y = (v[i].y - mu) * rstd * g4.y + b4.y;
        v[i].z = (v[i].z - mu) * rstd * g4.z + b4.z;
        v[i].w = (v[i].w - mu) * rstd * g4.w + b4.w;
        uint2 hp = make_uint2(pack_h2(v[i].x, v[i].y), pack_h2(v[i].z, v[i].w));
        *(uint2*)&g_xnh[(size_t)n * DDIM + (i * 32 + lane) * 4] = hp;
    }

    float dp[NEXP];
    #pragma unroll
    for (int e = 0; e < NEXP; e++) {
        const float4* r4 = (const float4*)(rw + (size_t)e * DDIM);
        float d = 0.f;
        #pragma unroll
        for (int i = 0; i < 8; i++) {
            float4 r = r4[i * 32 + lane];
            d += (v[i].x * r.x + v[i].y * r.y) + (v[i].z * r.z + v[i].w * r.w);
        }
        #pragma unroll
        for (int o = 16; o; o >>= 1) d += __shfl_xor_sync(0xffffffffu, d, o);
        dp[e] = d;
    }

    if (lane == 0) {
        if (write_logits) {
            #pragma unroll
            for (int e = 0; e < NEXP; e++) logits_out[(size_t)n * NEXP + e] = dp[e];
        }
        int i0 = 0;
        #pragma unroll
        for (int e = 1; e < NEXP; e++) if (dp[e] > dp[i0]) i0 = e;
        int i1 = (i0 == 0) ? 1 : 0;
        #pragma unroll
        for (int e = 0; e < NEXP; e++) if (e != i0 && dp[e] > dp[i1]) i1 = e;
        float q = expf(dp[i1] - dp[i0]);
        float inv = 1.0f / (1.0f + q);
        g_prob[2 * n]     = inv;
        g_prob[2 * n + 1] = q * inv;
        int p0 = atomicAdd(&g_cnt[i0], 1); g_slots[i0 * NTOK + p0] = 2 * n;
        int p1 = atomicAdd(&g_cnt[i1], 1); g_slots[i1 * NTOK + p1] = 2 * n + 1;
    }
}

// ---------------- kernel 2: element-wise fp32 -> fp16 weight convert -------
__global__ __launch_bounds__(256)
void wconv1_kernel(const float* __restrict__ w)
{
    size_t off = ((size_t)blockIdx.x * 256 + threadIdx.x) * 8;
    float4 a = *(const float4*)(w + off);
    float4 b = *(const float4*)(w + off + 4);
    uint4 pk;
    pk.x = pack_h2(a.x, a.y); pk.y = pack_h2(a.z, a.w);
    pk.z = pack_h2(b.x, b.y); pk.w = pack_h2(b.z, b.w);
    *(uint4*)(g_B1 + off) = pk;
}
__global__ __launch_bounds__(256)
void wconv2_kernel(const float* __restrict__ w)
{
    size_t off = ((size_t)blockIdx.x * 256 + threadIdx.x) * 8;
    float4 a = *(const float4*)(w + off);
    float4 b = *(const float4*)(w + off + 4);
    uint4 pk;
    pk.x = pack_h2(a.x, a.y); pk.y = pack_h2(a.z, a.w);
    pk.z = pack_h2(b.x, b.y); pk.w = pack_h2(b.z, b.w);
    *(uint4*)(g_B2 + off) = pk;
}

// ---------------- kernels 3/4: grouped fp16 GEMM via mma.sync --------------
// CTA tile 128x128, 8 warps (4x2), warp tile 32x64. K-chunk 64; 3-stage
// cp.async. A gathered (L1) / contiguous (L2); B in [K][N] layout loaded
// with ldmatrix.trans. L2 epilogue atomic-adds weighted GELU into d_out.
template<int LAYER>
__global__ __launch_bounds__(256, 2)
void mma_gemm(const float* __restrict__ bias_all,
              const float* __restrict__ mask,
              float* __restrict__ outp)
{
    constexpr int Kd = (LAYER == 1) ? DDIM : HDIM;
    constexpr int Nd = (LAYER == 1) ? HDIM : ODIM;
    constexpr int NCH = Kd / 64;
    constexpr int STAGE_BYTES = 32768;   // A 16K + B 16K
    const __half* __restrict__ Ball = (LAYER == 1) ? g_B1 : g_B2;

    const int e = blockIdx.z;
    const int cnt = g_cnt[e];
    const int m0 = blockIdx.x * 128;
    if (m0 >= cnt) return;
    const int n0 = blockIdx.y * 128;

    extern __shared__ __align__(1024) char smem[];
    const uint32_t smem_u = smem_to_u32(smem);
    __shared__ const __half* sArow[128];

    const int tid = threadIdx.x;
    const int lane = tid & 31;
    const int wid = tid >> 5;
    const int wm = wid >> 1;
    const int wn = wid & 1;

    if (tid < 128) {
        int r = m0 + tid;
        if (LAYER == 1) {
            int slot = (r < cnt) ? g_slots[e * NTOK + r] : g_slots[e * NTOK];
            sArow[tid] = g_xnh + (size_t)(slot >> 1) * DDIM;
        } else {
            sArow[tid] = g_A2 + ((size_t)e * EMAX + r) * HDIM;
        }
    }

    // B base: element (row k=0, col n0) of expert e's [Kd][Nd] panel
    const __half* Bbase = Ball + (size_t)e * Kd * Nd + n0;

    const int lr = tid >> 3;          // A: 4 rows/thread, stride 32
    const int lch = tid & 7;          // 16B chunk in 128B A row
    const uint32_t lsw = (uint32_t)(lch * 16) ^ (uint32_t)((lr & 7) << 4);
    const int bkk = tid >> 4;         // B: 4 K-rows/thread, stride 16
    const int bg16 = tid & 15;        // 16B granule in 256B B row

    float acc[2][8][4];
    #pragma unroll
    for (int i = 0; i < 2; i++)
        #pragma unroll
        for (int j = 0; j < 8; j++)
            #pragma unroll
            for (int q = 0; q < 4; q++) acc[i][j][q] = 0.f;

    __syncthreads();   // sArow visible before first load

    auto load_stage = [&](int c, int st) {
        const int col = c * 64;       // element (A) / K-row (B) offset of chunk
        const uint32_t sA = smem_u + st * STAGE_BYTES;
        const uint32_t sB = sA + 16384;
        #pragma unroll
        for (int l = 0; l < 4; l++) {
            int r = lr + l * 32;
            CP_ASYNC16(sA + (uint32_t)(r * 128) + lsw,
                       (const char*)(sArow[r] + col) + lch * 16);
        }
        #pragma unroll
        for (int l = 0; l < 4; l++) {
            int kk = bkk + l * 16;
            CP_ASYNC16(sB + (uint32_t)(kk * 256) +
                           (uint32_t)((bg16 * 16) ^ ((kk & 7) << 4)),
                       (const char*)(Bbase + (size_t)(col + kk) * Nd) + bg16 * 16);
        }
    };

    const int rowA0 = wm * 32 + (lane & 15);
    const int kbA = (lane >> 4) * 8;
    const int gq = lane >> 3, l7 = lane & 7;

    auto compute_stage = [&](int st) {
        const uint32_t sA = smem_u + st * STAGE_BYTES;
        const uint32_t sB = sA + 16384;
        #pragma unroll
        for (int ks = 0; ks < 4; ks++) {
            uint32_t af[2][4], bf[4][4];
            #pragma unroll
            for (int mf = 0; mf < 2; mf++) {
                int row = rowA0 + mf * 16;
                uint32_t koff = (uint32_t)((ks * 16 + kbA) * 2) ^ (uint32_t)((row & 7) << 4);
                LDSM_X4(af[mf], sA + (uint32_t)(row * 128) + koff);
            }
            #pragma unroll
            for (int ng = 0; ng < 4; ng++) {
                int krow = ks * 16 + ((gq & 1) << 3) + l7;
                int ncol = wn * 64 + ng * 16 + (gq >> 1) * 8;
                uint32_t addr = sB + (uint32_t)(krow * 256) +
                                (uint32_t)((ncol * 2) ^ ((krow & 7) << 4));
                LDSM_X4_T(bf[ng], addr);
            }
            #pragma unroll
            for (int ng = 0; ng < 4; ng++)
                #pragma unroll
                for (int mf = 0; mf < 2; mf++) {
                    MMAH16816(acc[mf][2 * ng],     af[mf], bf[ng][0], bf[ng][1]);
                    MMAH16816(acc[mf][2 * ng + 1], af[mf], bf[ng][2], bf[ng][3]);
                }
        }
    };

    load_stage(0, 0); CP_COMMIT();
    load_stage(1, 1); CP_COMMIT();
    for (int c = 0; c < NCH; c++) {
        CP_WAIT1();
        __syncthreads();
        if (c + 2 < NCH) load_stage(c + 2, (c + 2) % 3);
        CP_COMMIT();
        compute_stage(c % 3);
    }

    // ---------------- epilogue --------------------------------------------
    const float* bias = bias_all + (size_t)e * Nd;
    const int rbase = m0 + wm * 32 + (lane >> 2);
    const int cbase = n0 + wn * 64 + (lane & 3) * 2;

    #pragma unroll
    for (int mf = 0; mf < 2; mf++) {
        #pragma unroll
        for (int cp = 0; cp < 2; cp++) {
            int row = rbase + mf * 16 + cp * 8;
            if (row >= cnt) continue;
            if (LAYER == 1) {
                __half* orow = g_A2 + ((size_t)e * EMAX + row) * HDIM;
                #pragma unroll
                for (int nf = 0; nf < 8; nf++) {
                    int col = cbase + nf * 8;
                    float v0 = gelu_exact(acc[mf][nf][2 * cp]     + bias[col]);
                    float v1 = gelu_exact(acc[mf][nf][2 * cp + 1] + bias[col + 1]);
                    *(uint32_t*)&orow[col] = pack_h2(v0, v1);
                }
            } else {
                int slot = g_slots[e * NTOK + row];
                int token = slot >> 1;
                float p = g_prob[slot] * mask[token];
                float* orow = outp + (size_t)token * ODIM;
                #pragma unroll
                for (int nf = 0; nf < 8; nf++) {
                    int col = cbase + nf * 8;
                    float v0 = gelu_exact(acc[mf][nf][2 * cp]     + bias[col]);
                    float v1 = gelu_exact(acc[mf][nf][2 * cp + 1] + bias[col + 1]);
                    atomicAdd(&orow[col],     p * v0);
                    atomicAdd(&orow[col + 1], p * v1);
                }
            }
        }
    }
}

// ---------------- launch ----------------------------------------------------
extern "C" void kernel_launch(void* const* d_in, const int* in_sizes, int n_in,
                              void* d_out, int out_size)
{
    const float* x     = (const float*)d_in[0];
    const float* mask  = (const float*)d_in[1];
    const float* gamma = (const float*)d_in[2];
    const float* beta  = (const float*)d_in[3];
    const float* rw    = (const float*)d_in[4];
    const float* w1    = (const float*)d_in[5];
    const float* b1    = (const float*)d_in[6];
    const float* w2    = (const float*)d_in[7];
    const float* b2    = (const float*)d_in[8];
    float* out = (float*)d_out;

    const int TBO = NTOK * ODIM;
    const int write_logits = (out_size >= TBO + NTOK * NEXP) ? 1 : 0;
    const int DSMEM = 98304;   // 3 stages x (16K A + 16K B)

    static int attr_done = 0;
    if (!attr_done) {
        cudaFuncSetAttribute(mma_gemm<1>, cudaFuncAttributeMaxDynamicSharedMemorySize, DSMEM);
        cudaFuncSetAttribute(mma_gemm<2>, cudaFuncAttributeMaxDynamicSharedMemorySize, DSMEM);
        attr_done = 1;
    }

    zero_out_kernel<<<TBO / 1024, 256>>>(out);
    ln_router_kernel<<<NTOK / 8, 256>>>(x, gamma, beta, rw, out + TBO, write_logits);
    wconv1_kernel<<<8192, 256>>>(w1);
    wconv2_kernel<<<8192, 256>>>(w2);
    mma_gemm<1><<<dim3(EMAX / 128, HDIM / 128, NEXP), 256, DSMEM>>>(b1, mask, nullptr);
    mma_gemm<2><<<dim3(EMAX / 128, ODIM / 128, NEXP), 256, DSMEM>>>(b2, mask, out);
}